// round 6
// baseline (speedup 1.0000x reference)
#include <cuda_runtime.h>
#include <cstdint>

// GRU B=64,T=4096,F=100,H=200,O=1. 32 clusters x 4 CTAs, 640 thr/CTA (20 warps).
// Phase A: CTA-private gx = x·Wi into scratch. Phase B: recurrence, Wh in registers
// (52 floats/thread, K-quarter split), h broadcast from SMEM, DSMEM h exchange,
// split cluster arrive/wait per step, hnew -> global scratch. Phase C: y GEMV kernel.

#define Bq      64
#define Tq      4096
#define Fq      100
#define Hq      200
#define G3      600
#define BT      (Bq * Tq)
#define CLUSTER 4
#define BG      2
#define JPC     50
#define NTHR    640
#define KQ      52               // K-quarter of padded 208
#define TT      16               // phase-A tile rows
#define GRID    128

__device__ float g_gx[(size_t)GRID * Tq * BG * 160];   // 671 MB, CTA-private [t][b][160]
__device__ float g_h [(size_t)BT * Hq];                // 210 MB, [row=b*Tq+t][200]

__device__ __forceinline__ uint32_t smem_u32(const void* p) {
    return (uint32_t)__cvta_generic_to_shared(p);
}
__device__ __forceinline__ void st_cluster_f32(uint32_t laddr, uint32_t rr, float v) {
    uint32_t ra;
    asm volatile("mapa.shared::cluster.u32 %0, %1, %2;" : "=r"(ra) : "r"(laddr), "r"(rr));
    asm volatile("st.shared::cluster.f32 [%0], %1;" :: "r"(ra), "f"(v) : "memory");
}
__device__ __forceinline__ void ffma2(unsigned long long& acc,
                                      unsigned long long a, unsigned long long b) {
    asm("fma.rn.f32x2 %0, %1, %2, %0;" : "+l"(acc) : "l"(a), "l"(b));
}
__device__ __forceinline__ float fold2(unsigned long long a, unsigned long long b) {
    unsigned long long s;
    asm("add.rn.f32x2 %0, %1, %2;" : "=l"(s) : "l"(a), "l"(b));
    return __uint_as_float((unsigned)s) + __uint_as_float((unsigned)(s >> 32));
}
__device__ __forceinline__ unsigned long long pack2(float a, float b) {
    return (unsigned long long)__float_as_uint(a) |
           ((unsigned long long)__float_as_uint(b) << 32);
}
__device__ __forceinline__ float sigf(float x) {
    return __fdividef(1.0f, 1.0f + __expf(-x));
}
__device__ __forceinline__ float tanh_fast(float x) {
    return 2.0f * sigf(2.0f * x) - 1.0f;
}

struct __align__(16) Smem {
    float h[2][BG][208];        // parity, batch (pads 200..207 zeroed)   6656 B
    float gh[4][BG][160];       // K-quarter partials                     5120 B
    float bi_s[160];
    float bhn_s[64];
    float xs[BG][TT][112];      // phase-A x staging (pads 100..111 = 0) 14336 B
    float part[TT][NTHR];       // phase-A partial dots                  40960 B
};

__global__ void __launch_bounds__(NTHR, 1)
gru_kernel(const float* __restrict__ x,  const float* __restrict__ Wi,
           const float* __restrict__ bi, const float* __restrict__ Wh,
           const float* __restrict__ bhn, float* __restrict__ out)
{
    extern __shared__ char smraw[];
    Smem* sm = reinterpret_cast<Smem*>(smraw);
    const int tid = threadIdx.x;
    uint32_t rank;
    asm("mov.u32 %0, %%cluster_ctarank;" : "=r"(rank));
    const int b0g = (blockIdx.x >> 2) * BG;
    float* gsl = &g_gx[(size_t)blockIdx.x * Tq * (BG * 160)];
    (void)out;

    // ---- one-time SMEM init ----
    for (int i = tid; i < 2 * BG * 208; i += NTHR)
        (&sm->h[0][0][0])[i] = 0.f;
    for (int i = tid; i < 160; i += NTHR) {
        float v = 0.f;
        if (i < 150) { int g = i / JPC, jj = i - g * JPC; v = bi[g * Hq + (int)rank * JPC + jj]; }
        sm->bi_s[i] = v;
    }
    if (tid < JPC) sm->bhn_s[tid] = bhn[(int)rank * JPC + tid];
    for (int i = tid; i < BG * TT * 12; i += NTHR) {        // xs pad cols 100..111
        int b2 = i / (TT * 12), rem = i - b2 * (TT * 12);
        sm->xs[b2][rem / 12][100 + rem % 12] = 0.f;
    }

    // ================= Phase A: gx = x · Wi (CTA-private slice) =================
    {
        const int k2 = tid & 1, ab = (tid >> 1) & 1, ac = tid >> 2;   // 640 tasks
        const bool act = (ac < 150);
        int gcol = 0;
        if (act) { int g = ac / JPC, j2 = ac - g * JPC; gcol = g * Hq + (int)rank * JPC + j2; }

        ulonglong2 wa[7];    // 28 floats... covers k = k2*56 + 0..27*? -> 7*4 = 28? NO: 7 ull2 = 28 floats
        // 7 ulonglong2 = 28 bytes*... (7 * 16B = 112B = 28 floats) -> covers 28 of 56: need 14 ull2? No:
        // K-slice is 56 floats = 224B = 14 ulonglong -> 7 ulonglong2 holds 28 floats. Use 14 ull via 7 ull2? 
        // Correct: 56 floats = 14 ull = 7 ull2? 7*2 ull = 14 ull = 28 floats. WRONG. Use wa2[14] ull:
        (void)wa;
        unsigned long long wb[28];   // 56 floats = 28 packed f32x2
        #pragma unroll
        for (int q = 0; q < 28; ++q) {
            int k0 = k2 * 56 + q * 2;
            float v0 = (act && k0     < Fq) ? Wi[(size_t)(k0    ) * G3 + gcol] : 0.f;
            float v1 = (act && k0 + 1 < Fq) ? Wi[(size_t)(k0 + 1) * G3 + gcol] : 0.f;
            wb[q] = pack2(v0, v1);
        }

        for (int t0 = 0; t0 < Tq; t0 += TT) {
            __syncthreads();
            for (int i = tid; i < BG * TT * Fq; i += NTHR) {
                int b2 = i / (TT * Fq), rem = i - b2 * (TT * Fq);
                int r = rem / Fq, f = rem - r * Fq;
                sm->xs[b2][r][f] =
                    x[(size_t)(b0g + b2) * (Tq * Fq) + (size_t)(t0 + r) * Fq + f];
            }
            __syncthreads();
            #pragma unroll 1
            for (int r = 0; r < TT; ++r) {
                const ulonglong2* vp =
                    reinterpret_cast<const ulonglong2*>(&sm->xs[ab][r][k2 * 56]);
                unsigned long long a0 = 0, a1 = 0;
                #pragma unroll
                for (int q = 0; q < 14; ++q) {
                    ulonglong2 v = vp[q];
                    ffma2(a0, wb[2 * q], v.x);
                    ffma2(a1, wb[2 * q + 1], v.y);
                }
                sm->part[r][tid] = fold2(a0, a1);
            }
            __syncthreads();
            for (int o = tid; o < TT * 320; o += NTHR) {
                int r = o / 320, rem = o - r * 320;
                int cc = rem >> 1, b2 = rem & 1;
                int pi = (cc << 2) | (b2 << 1);
                gsl[(size_t)(t0 + r) * (BG * 160) + b2 * 160 + cc] =
                    sm->part[r][pi] + sm->part[r][pi | 1];
            }
        }
    }
    __syncthreads();   // gsl visible CTA-wide

    // ================= Phase B: recurrence =================
    const int wid = tid >> 5, lane = tid & 31;
    const int kq  = wid / 5, cg = wid - kq * 5;     // kq 0..3, cg 0..4
    const int col = cg * 32 + lane;                 // 0..159 (150 real)

    // register-resident Wh: column col, K-quarter slice (52 floats = 26 packed)
    unsigned long long wreg[26];
    {
        int gcol = 0;
        const bool real = (col < 150);
        if (real) {
            int g = col / JPC, jj2 = col - g * JPC;
            gcol = g * Hq + (int)rank * JPC + jj2;
        }
        #pragma unroll
        for (int q = 0; q < 26; ++q) {
            int k0 = kq * KQ + q * 2;
            float v0 = (real && k0     < Hq) ? Wh[(size_t)(k0    ) * G3 + gcol] : 0.f;
            float v1 = (real && k0 + 1 < Hq) ? Wh[(size_t)(k0 + 1) * G3 + gcol] : 0.f;
            wreg[q] = pack2(v0, v1);
        }
    }

    const int eb = tid >> 6, jj = tid & 63;
    const bool epi = (tid < 128) && (jj < JPC);
    const int jg = (int)rank * JPC + jj;
    const size_t gxo   = epi ? ((size_t)eb * 160 + jj) : 0;
    const size_t hbase = epi ? ((size_t)(b0g + eb) * Tq) * Hq + jg : 0;

    __syncthreads();
    asm volatile("barrier.cluster.arrive.aligned;" ::: "memory");   // initial token

    // preload gx(t=0)
    float gr = 0.f, gz = 0.f, gn = 0.f;
    if (epi) { gr = gsl[gxo]; gz = gsl[gxo + 50]; gn = gsl[gxo + 100]; }

    int par = 0;
    for (int t = 0; t < Tq; ++t) {
        const int nxt = par ^ 1;

        asm volatile("barrier.cluster.wait.aligned;" ::: "memory");  // h[par] ready

        // ---- dot: K-quarter, both batches, warp-uniform broadcast loads ----
        {
            const ulonglong2* vp0 = reinterpret_cast<const ulonglong2*>(&sm->h[par][0][kq * KQ]);
            const ulonglong2* vp1 = reinterpret_cast<const ulonglong2*>(&sm->h[par][1][kq * KQ]);
            unsigned long long a0x = 0, a0y = 0, a1x = 0, a1y = 0;
            #pragma unroll
            for (int q = 0; q < 13; ++q) {
                ulonglong2 v0 = vp0[q], v1 = vp1[q];
                ffma2(a0x, wreg[2 * q], v0.x); ffma2(a0y, wreg[2 * q + 1], v0.y);
                ffma2(a1x, wreg[2 * q], v1.x); ffma2(a1y, wreg[2 * q + 1], v1.y);
            }
            sm->gh[kq][0][col] = fold2(a0x, a0y);
            sm->gh[kq][1][col] = fold2(a1x, a1y);
        }
        __syncthreads();

        // ---- epilogue: gates, h update, DSMEM exchange, h -> scratch ----
        if (epi) {
            int cr = jj, cz = JPC + jj, cn = 2 * JPC + jj;
            float sr = (sm->gh[0][eb][cr] + sm->gh[1][eb][cr])
                     + (sm->gh[2][eb][cr] + sm->gh[3][eb][cr]);
            float sz = (sm->gh[0][eb][cz] + sm->gh[1][eb][cz])
                     + (sm->gh[2][eb][cz] + sm->gh[3][eb][cz]);
            float sn = (sm->gh[0][eb][cn] + sm->gh[1][eb][cn])
                     + (sm->gh[2][eb][cn] + sm->gh[3][eb][cn]);
            float r = sigf(gr + sr + sm->bi_s[cr]);
            float z = sigf(gz + sz + sm->bi_s[cz]);
            float n = tanh_fast(gn + sm->bi_s[cn] + r * (sn + sm->bhn_s[jj]));
            float hold = sm->h[par][eb][jg];
            float hnew = n + z * (hold - n);
            uint32_t la = smem_u32(&sm->h[nxt][eb][jg]);
            #pragma unroll
            for (uint32_t rr = 0; rr < CLUSTER; ++rr) st_cluster_f32(la, rr, hnew);
            g_h[hbase + (size_t)t * Hq] = hnew;
        }
        asm volatile("barrier.cluster.arrive.aligned;" ::: "memory");  // release pushes

        // prefetch gx(t+1) between arrive and next wait
        if (epi && (t + 1 < Tq)) {
            const float* p = gsl + (size_t)(t + 1) * (BG * 160) + gxo;
            gr = p[0]; gz = p[50]; gn = p[100];
        }
        par = nxt;
    }
    asm volatile("barrier.cluster.wait.aligned;" ::: "memory");   // balance final arrive
}

// ================= Phase C: y = h · Wo + bo =================
__global__ void __launch_bounds__(256)
y_kernel(const float* __restrict__ Wo, const float* __restrict__ bo,
         float* __restrict__ out)
{
    __shared__ float wos[Hq];
    const int tid = threadIdx.x;
    if (tid < Hq) wos[tid] = Wo[tid];
    __syncthreads();
    const float bo0 = bo[0];
    const int lane = tid & 31;
    const int gw   = (blockIdx.x * 256 + tid) >> 5;
    const int nw   = (gridDim.x * 256) >> 5;
    for (int row = gw; row < BT; row += nw) {
        const float* hr = g_h + (size_t)row * Hq;
        float s = 0.f;
        #pragma unroll
        for (int k = lane; k < Hq; k += 32) s = fmaf(hr[k], wos[k], s);
        #pragma unroll
        for (int m = 16; m > 0; m >>= 1) s += __shfl_xor_sync(0xffffffffu, s, m);
        if (lane == 0) out[row] = s + bo0;
    }
}

extern "C" void kernel_launch(void* const* d_in, const int* in_sizes, int n_in,
                              void* d_out, int out_size) {
    (void)in_sizes; (void)n_in; (void)out_size;
    const float* x   = (const float*)d_in[0];
    const float* Wi  = (const float*)d_in[1];
    const float* bi  = (const float*)d_in[2];
    const float* Wh  = (const float*)d_in[3];
    const float* bhn = (const float*)d_in[4];
    const float* Wo  = (const float*)d_in[5];
    const float* bo  = (const float*)d_in[6];
    float* out = (float*)d_out;

    cudaFuncSetAttribute(gru_kernel, cudaFuncAttributeMaxDynamicSharedMemorySize,
                         (int)sizeof(Smem));
    cudaLaunchConfig_t cfg = {};
    cfg.gridDim  = dim3(GRID, 1, 1);
    cfg.blockDim = dim3(NTHR, 1, 1);
    cfg.dynamicSmemBytes = sizeof(Smem);
    cfg.stream = 0;
    cudaLaunchAttribute attr[1];
    attr[0].id = cudaLaunchAttributeClusterDimension;
    attr[0].val.clusterDim.x = CLUSTER;
    attr[0].val.clusterDim.y = 1;
    attr[0].val.clusterDim.z = 1;
    cfg.attrs = attr;
    cfg.numAttrs = 1;
    cudaLaunchKernelEx(&cfg, gru_kernel, x, Wi, bi, Wh, bhn, out);

    y_kernel<<<592, 256>>>(Wo, bo, out);
}

// round 7
// speedup vs baseline: 1.3370x; 1.3370x over previous
#include <cuda_runtime.h>
#include <cstdint>

// GRU B=64,T=4096,F=100,H=200,O=1. 32 clusters x 4 CTAs, 320 thr (proven reg budget).
// Phase A: CTA-private gx = x·Wi -> scratch (R5 version, verified).
// Phase B: recurrence; Wh register-resident (52 packed regs, K-half split); h broadcast
//   from SMEM; DSMEM h exchange; ONE split cluster arrive/wait per step (doubles as the
//   intra-CTA epilogue->dot barrier); gx prefetched 2 steps ahead; hnew -> g_h scratch.
// Phase C: y = h·Wo + bo GEMV (measured 47us).

#define Bq      64
#define Tq      4096
#define Fq      100
#define Hq      200
#define G3      600
#define BT      (Bq * Tq)
#define CLUSTER 4
#define BG      2
#define JPC     50
#define NTHR    320
#define KHH     104              // K-half of padded 208
#define TT      32               // phase-A tile rows
#define GRID    128

__device__ float g_gx[(size_t)GRID * Tq * BG * 160];   // 671 MB CTA-private [t][b][160]
__device__ float g_h [(size_t)BT * Hq];                // 210 MB [row=b*Tq+t][200]

__device__ __forceinline__ uint32_t smem_u32(const void* p) {
    return (uint32_t)__cvta_generic_to_shared(p);
}
__device__ __forceinline__ void st_cluster_f32(uint32_t laddr, uint32_t rr, float v) {
    uint32_t ra;
    asm volatile("mapa.shared::cluster.u32 %0, %1, %2;" : "=r"(ra) : "r"(laddr), "r"(rr));
    asm volatile("st.shared::cluster.f32 [%0], %1;" :: "r"(ra), "f"(v) : "memory");
}
__device__ __forceinline__ void ffma2(unsigned long long& acc,
                                      unsigned long long a, unsigned long long b) {
    asm("fma.rn.f32x2 %0, %1, %2, %0;" : "+l"(acc) : "l"(a), "l"(b));
}
__device__ __forceinline__ float fold2(unsigned long long a, unsigned long long b) {
    unsigned long long s;
    asm("add.rn.f32x2 %0, %1, %2;" : "=l"(s) : "l"(a), "l"(b));
    return __uint_as_float((unsigned)s) + __uint_as_float((unsigned)(s >> 32));
}
__device__ __forceinline__ unsigned long long pack2(float a, float b) {
    return (unsigned long long)__float_as_uint(a) |
           ((unsigned long long)__float_as_uint(b) << 32);
}
__device__ __forceinline__ float sigf(float x) {
    return __fdividef(1.0f, 1.0f + __expf(-x));
}
__device__ __forceinline__ float tanh_fast(float x) {
    return 2.0f * sigf(2.0f * x) - 1.0f;
}

struct __align__(16) Smem {
    float h[2][BG][208];        // parity, batch (pads 200..207 zeroed)
    float gh[2][BG][160];       // K-half partials [kh][b][col]
    float bi_s[160];
    float bhn_s[64];
    float xs[BG][TT][104];      // phase-A x staging (pads 100..103 zeroed)
};

__global__ void __launch_bounds__(NTHR, 1)
gru_kernel(const float* __restrict__ x,  const float* __restrict__ Wi,
           const float* __restrict__ bi, const float* __restrict__ Wh,
           const float* __restrict__ bhn)
{
    extern __shared__ char smraw[];
    Smem* sm = reinterpret_cast<Smem*>(smraw);
    const int tid = threadIdx.x;
    uint32_t rank;
    asm("mov.u32 %0, %%cluster_ctarank;" : "=r"(rank));
    const int b0g = (blockIdx.x >> 2) * BG;
    float* gsl = &g_gx[(size_t)blockIdx.x * Tq * (BG * 160)];

    // ---- one-time SMEM init ----
    for (int i = tid; i < 2 * BG * 208; i += NTHR)
        (&sm->h[0][0][0])[i] = 0.f;
    for (int i = tid; i < 160; i += NTHR) {
        float v = 0.f;
        if (i < 150) { int g = i / JPC, jj = i - g * JPC; v = bi[g * Hq + (int)rank * JPC + jj]; }
        sm->bi_s[i] = v;
    }
    if (tid < JPC) sm->bhn_s[tid] = bhn[(int)rank * JPC + tid];
    for (int i = tid; i < BG * TT * 4; i += NTHR) {
        int b2 = i / (TT * 4), rem = i - b2 * (TT * 4);
        sm->xs[b2][rem >> 2][100 + (rem & 3)] = 0.f;
    }

    // ================= Phase A: gx = x · Wi (CTA-private slice) =================
    {
        const int c   = tid >> 1;        // 0..159 (c<150 real)
        const int b   = tid & 1;
        const bool act = (c < 150);
        int gcol = 0;
        if (act) { int g = c / JPC, j2 = c - g * JPC; gcol = g * Hq + (int)rank * JPC + j2; }

        ulonglong2 wr[26];               // k = 0..103 (100 real + 4 zero pad)
        #pragma unroll
        for (int q = 0; q < 26; ++q) {
            float v[4];
            #pragma unroll
            for (int r = 0; r < 4; ++r) {
                int k = q * 4 + r;
                v[r] = (act && k < Fq) ? Wi[(size_t)k * G3 + gcol] : 0.f;
            }
            wr[q].x = pack2(v[0], v[1]);
            wr[q].y = pack2(v[2], v[3]);
        }

        for (int t0 = 0; t0 < Tq; t0 += TT) {
            __syncthreads();
            for (int i = tid; i < BG * TT * Fq; i += NTHR) {
                int b2 = i / (TT * Fq), rem = i - b2 * (TT * Fq);
                int r = rem / Fq, f = rem - r * Fq;
                sm->xs[b2][r][f] =
                    x[(size_t)(b0g + b2) * (Tq * Fq) + (size_t)(t0 + r) * Fq + f];
            }
            __syncthreads();
            if (act) {
                for (int r = 0; r < TT; ++r) {
                    const ulonglong2* vp = reinterpret_cast<const ulonglong2*>(sm->xs[b][r]);
                    unsigned long long a0 = 0, a1 = 0;
                    #pragma unroll
                    for (int q = 0; q < 26; ++q) {
                        ulonglong2 v = vp[q];
                        ffma2(a0, wr[q].x, v.x);
                        ffma2(a1, wr[q].y, v.y);
                    }
                    gsl[(size_t)(t0 + r) * (BG * 160) + b * 160 + c] = fold2(a0, a1);
                }
            }
        }
    }
    __syncthreads();   // gsl visible CTA-wide

    // ================= Phase B: recurrence =================
    const int wid  = tid >> 5, lane = tid & 31;
    const int kh   = (wid >= 5);                         // K-half
    const int col  = (kh ? wid - 5 : wid) * 32 + lane;   // 0..159 (150 real)

    // register-resident Wh: column col, K-half slice (104 floats = 52 regs)
    ulonglong2 wreg[26];
    {
        int gcol = 0;
        const bool real = (col < 150);
        if (real) {
            int g = col / JPC, jj = col - g * JPC;
            gcol = g * Hq + (int)rank * JPC + jj;
        }
        #pragma unroll
        for (int q = 0; q < 26; ++q) {
            float v[4];
            #pragma unroll
            for (int r = 0; r < 4; ++r) {
                int k = kh * KHH + q * 4 + r;
                v[r] = (real && k < Hq) ? Wh[(size_t)k * G3 + gcol] : 0.f;
            }
            wreg[q].x = pack2(v[0], v[1]);
            wreg[q].y = pack2(v[2], v[3]);
        }
    }

    const int eb = tid >> 6, jj = tid & 63;      // epilogue map (tid<128, jj<50)
    const bool epi = (tid < 128) && (jj < JPC);
    const int jg = (int)rank * JPC + jj;
    const size_t gxo   = epi ? ((size_t)eb * 160 + jj) : 0;
    const size_t hbase = epi ? ((size_t)(b0g + eb) * Tq) * Hq + jg : 0;

    // 2-deep gx register pipeline: g0 = gx(t), g1 = gx(t+1)
    float g0r = 0.f, g0z = 0.f, g0n = 0.f;
    float g1r = 0.f, g1z = 0.f, g1n = 0.f;
    if (epi) {
        g0r = gsl[gxo];       g0z = gsl[gxo + 50];       g0n = gsl[gxo + 100];
        const float* p = gsl + (BG * 160) + gxo;
        g1r = p[0];           g1z = p[50];               g1n = p[100];
    }

    __syncthreads();
    asm volatile("barrier.cluster.arrive.aligned;" ::: "memory");   // initial token

    int par = 0;
    for (int t = 0; t < Tq; ++t) {
        const int nxt = par ^ 1;

        // all CTAs' h[par] pushes complete; also orders epilogue(t-1) vs dot(t) in-CTA
        asm volatile("barrier.cluster.wait.aligned;" ::: "memory");

        // ---- dot: K-half, both batches, warp-uniform broadcast loads ----
        {
            const ulonglong2* vp0 = reinterpret_cast<const ulonglong2*>(&sm->h[par][0][kh * KHH]);
            const ulonglong2* vp1 = reinterpret_cast<const ulonglong2*>(&sm->h[par][1][kh * KHH]);
            unsigned long long a0x = 0, a0y = 0, a1x = 0, a1y = 0;
            #pragma unroll
            for (int q = 0; q < 26; ++q) {
                ulonglong2 v0 = vp0[q], v1 = vp1[q];
                ffma2(a0x, wreg[q].x, v0.x); ffma2(a0y, wreg[q].y, v0.y);
                ffma2(a1x, wreg[q].x, v1.x); ffma2(a1y, wreg[q].y, v1.y);
            }
            sm->gh[kh][0][col] = fold2(a0x, a0y);
            sm->gh[kh][1][col] = fold2(a1x, a1y);
        }
        __syncthreads();

        // ---- epilogue: gates, h update, DSMEM exchange, h -> scratch ----
        if (epi) {
            int cr = jj, cz = JPC + jj, cn = 2 * JPC + jj;
            float ar  = g0r + sm->gh[0][eb][cr] + sm->gh[1][eb][cr] + sm->bi_s[cr];
            float az  = g0z + sm->gh[0][eb][cz] + sm->gh[1][eb][cz] + sm->bi_s[cz];
            float ghn = sm->gh[0][eb][cn] + sm->gh[1][eb][cn] + sm->bhn_s[jj];
            float r = sigf(ar), z = sigf(az);
            float n = tanh_fast(g0n + sm->bi_s[cn] + r * ghn);
            float hold = sm->h[par][eb][jg];
            float hnew = n + z * (hold - n);
            uint32_t la = smem_u32(&sm->h[nxt][eb][jg]);
            #pragma unroll
            for (uint32_t rr = 0; rr < CLUSTER; ++rr) st_cluster_f32(la, rr, hnew);
            g_h[hbase + (size_t)t * Hq] = hnew;
        }
        // release h pushes cluster-wide; rendezvous consumed at next wait
        asm volatile("barrier.cluster.arrive.aligned;" ::: "memory");

        // shift gx pipeline; prefetch t+2 (covered by ~2 full steps)
        g0r = g1r; g0z = g1z; g0n = g1n;
        if (epi && (t + 2 < Tq)) {
            const float* p = gsl + (size_t)(t + 2) * (BG * 160) + gxo;
            g1r = p[0]; g1z = p[50]; g1n = p[100];
        }
        par = nxt;
    }
    asm volatile("barrier.cluster.wait.aligned;" ::: "memory");   // balance final arrive
}

// ================= Phase C: y = h · Wo + bo =================
__global__ void __launch_bounds__(256)
y_kernel(const float* __restrict__ Wo, const float* __restrict__ bo,
         float* __restrict__ out)
{
    __shared__ float wos[Hq];
    const int tid = threadIdx.x;
    if (tid < Hq) wos[tid] = Wo[tid];
    __syncthreads();
    const float bo0 = bo[0];
    const int lane = tid & 31;
    const int gw   = (blockIdx.x * 256 + tid) >> 5;
    const int nw   = (gridDim.x * 256) >> 5;
    for (int row = gw; row < BT; row += nw) {
        const float* hr = g_h + (size_t)row * Hq;
        float s = 0.f;
        #pragma unroll
        for (int k = lane; k < Hq; k += 32) s = fmaf(hr[k], wos[k], s);
        #pragma unroll
        for (int m = 16; m > 0; m >>= 1) s += __shfl_xor_sync(0xffffffffu, s, m);
        if (lane == 0) out[row] = s + bo0;
    }
}

extern "C" void kernel_launch(void* const* d_in, const int* in_sizes, int n_in,
                              void* d_out, int out_size) {
    (void)in_sizes; (void)n_in; (void)out_size;
    const float* x   = (const float*)d_in[0];
    const float* Wi  = (const float*)d_in[1];
    const float* bi  = (const float*)d_in[2];
    const float* Wh  = (const float*)d_in[3];
    const float* bhn = (const float*)d_in[4];
    const float* Wo  = (const float*)d_in[5];
    const float* bo  = (const float*)d_in[6];
    float* out = (float*)d_out;

    cudaFuncSetAttribute(gru_kernel, cudaFuncAttributeMaxDynamicSharedMemorySize,
                         (int)sizeof(Smem));
    cudaLaunchConfig_t cfg = {};
    cfg.gridDim  = dim3(GRID, 1, 1);
    cfg.blockDim = dim3(NTHR, 1, 1);
    cfg.dynamicSmemBytes = sizeof(Smem);
    cfg.stream = 0;
    cudaLaunchAttribute attr[1];
    attr[0].id = cudaLaunchAttributeClusterDimension;
    attr[0].val.clusterDim.x = CLUSTER;
    attr[0].val.clusterDim.y = 1;
    attr[0].val.clusterDim.z = 1;
    cfg.attrs = attr;
    cfg.numAttrs = 1;
    cudaLaunchKernelEx(&cfg, gru_kernel, x, Wi, bi, Wh, bhn);

    y_kernel<<<592, 256>>>(Wo, bo, out);
}